// round 9
// baseline (speedup 1.0000x reference)
#include <cuda_runtime.h>
#include <cuda_bf16.h>
#include <cstdint>

#define N_ROWS  100000
#define C_DIM   1024
#define OUT_DIM 256
#define TOPK_K  8
#define NPAIR   28
#define QDIM_V  2076
#define LN_EPS  1e-5f

// ---------------------------------------------------------------------------
// Device-global scratch (no cudaMalloc allowed)
// ---------------------------------------------------------------------------
__device__ float g_z [(size_t)N_ROWS * C_DIM];    // GEMM1 output (pre-LN)
__device__ float g_qc[(size_t)N_ROWS * C_DIM];    // cos(pi*tanh(z_ln))
__device__ float g_qs[(size_t)N_ROWS * C_DIM];    // sin(pi*tanh(z_ln))
__device__ float g_q [(size_t)N_ROWS * OUT_DIM];  // GEMM2 raw sums
__device__ float g_colsum [C_DIM];
__device__ float g_colsum2[C_DIM];
__device__ int   g_idx[TOPK_K];

// np.triu_indices(8, 1)
__constant__ int c_iu[NPAIR] = {0,0,0,0,0,0,0, 1,1,1,1,1,1, 2,2,2,2,2, 3,3,3,3, 4,4,4, 5,5, 6};
__constant__ int c_ju[NPAIR] = {1,2,3,4,5,6,7, 2,3,4,5,6,7, 3,4,5,6,7, 4,5,6,7, 5,6,7, 6,7, 7};

// ---------------------------------------------------------------------------
// Helpers
// ---------------------------------------------------------------------------
__device__ __forceinline__ uint32_t smem_u32(const void* p) {
    uint32_t a;
    asm("{ .reg .u64 t; cvta.to.shared.u64 t, %1; cvt.u32.u64 %0, t; }" : "=r"(a) : "l"(p));
    return a;
}
#define SWZ(o) ((o) ^ (((o) >> 3) & 0x70))

__device__ __forceinline__ void mma16816(float* d, const uint32_t* a, const uint32_t* b) {
    asm volatile("mma.sync.aligned.m16n8k16.row.col.f32.bf16.bf16.f32 "
        "{%0,%1,%2,%3}, {%4,%5,%6,%7}, {%8,%9}, {%0,%1,%2,%3};"
        : "+f"(d[0]), "+f"(d[1]), "+f"(d[2]), "+f"(d[3])
        : "r"(a[0]), "r"(a[1]), "r"(a[2]), "r"(a[3]), "r"(b[0]), "r"(b[1]));
}
__device__ __forceinline__ void ldsm_x4(uint32_t* r, uint32_t addr) {
    asm volatile("ldmatrix.sync.aligned.m8n8.x4.shared.b16 {%0,%1,%2,%3}, [%4];"
        : "=r"(r[0]), "=r"(r[1]), "=r"(r[2]), "=r"(r[3]) : "r"(addr));
}

// split fp32 x4 into bf16 hi/lo x4 (packed, memory order)
__device__ __forceinline__ void split4(float4 v, uint2& hi, uint2& lo) {
    __nv_bfloat16 h0 = __float2bfloat16_rn(v.x);
    __nv_bfloat16 h1 = __float2bfloat16_rn(v.y);
    __nv_bfloat16 h2 = __float2bfloat16_rn(v.z);
    __nv_bfloat16 h3 = __float2bfloat16_rn(v.w);
    __nv_bfloat16 l0 = __float2bfloat16_rn(v.x - __bfloat162float(h0));
    __nv_bfloat16 l1 = __float2bfloat16_rn(v.y - __bfloat162float(h1));
    __nv_bfloat16 l2 = __float2bfloat16_rn(v.z - __bfloat162float(h2));
    __nv_bfloat16 l3 = __float2bfloat16_rn(v.w - __bfloat162float(h3));
    hi.x = (uint32_t)__bfloat16_as_ushort(h0) | ((uint32_t)__bfloat16_as_ushort(h1) << 16);
    hi.y = (uint32_t)__bfloat16_as_ushort(h2) | ((uint32_t)__bfloat16_as_ushort(h3) << 16);
    lo.x = (uint32_t)__bfloat16_as_ushort(l0) | ((uint32_t)__bfloat16_as_ushort(l1) << 16);
    lo.y = (uint32_t)__bfloat16_as_ushort(l2) | ((uint32_t)__bfloat16_as_ushort(l3) << 16);
}

// ---------------------------------------------------------------------------
// Split-bf16 mma.sync GEMM with register-prefetch pipeline.
// Block 128x128, 512 threads, warp tile 32x32 (4x4 warp grid).
// A*B ~= Ah*Bh + Ah*Bl + Al*Bh  (fp32 accumulators)
// smem stage (64KB): Ah@0 | Al@16K | Bh@32K | Bl@48K, SW128 swizzle, K-chunk 64.
// G2=false: g_z = x @ Wproj^T + bias.  G2=true: g_q = [Qc|Qs] @ Wout[:, :2048]^T
// ---------------------------------------------------------------------------
template<int KT, bool G2>
__global__ void __launch_bounds__(512, 1)
gemm_mma(const float* __restrict__ A0, const float* __restrict__ B0,
         const float* __restrict__ bias)
{
    extern __shared__ char smem[];
    const uint32_t sbase = smem_u32(smem);
    const int tid  = threadIdx.x;
    const int lane = tid & 31;
    const int warp = tid >> 5;
    const int wm   = warp >> 2;            // 0..3
    const int wn   = warp & 3;             // 0..3
    const int n0   = blockIdx.x * 128;
    const long m0  = (long)blockIdx.y * 128;
    const long sA  = C_DIM;
    const long sB  = G2 ? QDIM_V : C_DIM;

    float acc[2][4][4];
#pragma unroll
    for (int mt = 0; mt < 2; mt++)
#pragma unroll
        for (int nt = 0; nt < 4; nt++)
#pragma unroll
            for (int j = 0; j < 4; j++) acc[mt][nt][j] = 0.f;

    // per-thread fill coordinates (4 iterations x (A,B))
    const int f_r = tid >> 4;              // 0..31 (+32*i)
    const int f_c = tid & 15;              // 0..15

    // gmem tile loader: chunk kt -> registers
    auto load_tiles = [&](int kt, float4* va, float4* vb) {
        const float* Ap; long acol;
        if (G2) {
            if (kt < KT / 2) { Ap = (const float*)g_qc; acol = (long)kt * 64; }
            else             { Ap = (const float*)g_qs; acol = (long)(kt - KT / 2) * 64; }
        } else { Ap = A0; acol = (long)kt * 64; }
        const long bcol = (long)kt * 64;
#pragma unroll
        for (int i = 0; i < 4; i++) {
            int r = f_r + i * 32;
            long arow = m0 + r;
            va[i] = (arow < N_ROWS)
                ? __ldg((const float4*)(Ap + arow * sA + acol + f_c * 4))
                : make_float4(0.f, 0.f, 0.f, 0.f);
            vb[i] = __ldg((const float4*)(B0 + (long)(n0 + r) * sB + bcol + f_c * 4));
        }
    };

    // ldmatrix per-lane address precompute (swizzle XOR depends only on row)
    const int a_r  = lane & 15;
    const int a_kb = (lane >> 4) << 4;
    const int b_r  = (lane & 7) | ((lane >> 4) << 3);
    const int b_kb = ((lane >> 3) & 1) << 4;
    uint32_t aoff[2], axr[2], boff[2], bxr[2];
#pragma unroll
    for (int mt = 0; mt < 2; mt++) {
        uint32_t o = (uint32_t)((wm * 32 + mt * 16 + a_r) * 128 + a_kb);
        axr[mt] = (o >> 3) & 0x70; aoff[mt] = o;
    }
#pragma unroll
    for (int bt = 0; bt < 2; bt++) {
        uint32_t o = (uint32_t)((wn * 32 + bt * 16 + b_r) * 128 + b_kb);
        bxr[bt] = (o >> 3) & 0x70; boff[bt] = o;
    }

    float4 va[4], vb[4];
    load_tiles(0, va, vb);

    for (int kt = 0; kt < KT; kt++) {
        // ---- store prefetched regs -> bf16 hi/lo swizzled smem ----
#pragma unroll
        for (int i = 0; i < 4; i++) {
            int r = f_r + i * 32;
            uint32_t off = SWZ((uint32_t)(r * 128 + f_c * 8));
            uint2 hi, lo;
            split4(va[i], hi, lo);
            *(uint2*)(smem + off)         = hi;
            *(uint2*)(smem + 16384 + off) = lo;
            split4(vb[i], hi, lo);
            *(uint2*)(smem + 32768 + off) = hi;
            *(uint2*)(smem + 49152 + off) = lo;
        }
        __syncthreads();

        // ---- issue next chunk's loads (latency hides under compute) ----
        float4 na[4], nb[4];
        if (kt + 1 < KT) load_tiles(kt + 1, na, nb);

        // ---- compute: 4 k16 steps x 3 split terms ----
#pragma unroll
        for (int ks = 0; ks < 4; ks++) {
            uint32_t ah[2][4], al[2][4], bh[4][2], bl[4][2];
#pragma unroll
            for (int mt = 0; mt < 2; mt++) {
                uint32_t ad = sbase + ((aoff[mt] + ks * 32) ^ axr[mt]);
                ldsm_x4(ah[mt], ad);
                ldsm_x4(al[mt], ad + 16384);
            }
#pragma unroll
            for (int bt = 0; bt < 2; bt++) {
                uint32_t bd = sbase + 32768 + ((boff[bt] + ks * 32) ^ bxr[bt]);
                uint32_t q[4];
                ldsm_x4(q, bd);
                bh[2*bt][0] = q[0]; bh[2*bt][1] = q[1];
                bh[2*bt+1][0] = q[2]; bh[2*bt+1][1] = q[3];
                ldsm_x4(q, bd + 16384);
                bl[2*bt][0] = q[0]; bl[2*bt][1] = q[1];
                bl[2*bt+1][0] = q[2]; bl[2*bt+1][1] = q[3];
            }
#pragma unroll
            for (int mt = 0; mt < 2; mt++)
#pragma unroll
                for (int nt = 0; nt < 4; nt++) {
                    mma16816(acc[mt][nt], ah[mt], bh[nt]);
                    mma16816(acc[mt][nt], ah[mt], bl[nt]);
                    mma16816(acc[mt][nt], al[mt], bh[nt]);
                }
        }

        if (kt + 1 < KT) {
#pragma unroll
            for (int i = 0; i < 4; i++) { va[i] = na[i]; vb[i] = nb[i]; }
        }
        __syncthreads();
    }

    // ---- epilogue: write fp32 (optionally + bias) ----
    float* Outp = G2 ? (float*)g_q : (float*)g_z;
    const long sOut = G2 ? OUT_DIM : C_DIM;
    const int qr = lane >> 2;
    const int qc = (lane & 3) * 2;
#pragma unroll
    for (int mt = 0; mt < 2; mt++)
#pragma unroll
        for (int nt = 0; nt < 4; nt++) {
            long m = m0 + wm * 32 + mt * 16 + qr;
            int  n = n0 + wn * 32 + nt * 8 + qc;
            float2 bv = make_float2(0.f, 0.f);
            if (!G2) bv = *(const float2*)(bias + n);
            if (m < N_ROWS) {
                float2 v = make_float2(acc[mt][nt][0] + bv.x, acc[mt][nt][1] + bv.y);
                *(float2*)(Outp + m * sOut + n) = v;
            }
            if (m + 8 < N_ROWS) {
                float2 v = make_float2(acc[mt][nt][2] + bv.x, acc[mt][nt][3] + bv.y);
                *(float2*)(Outp + (m + 8) * sOut + n) = v;
            }
        }
}

// ---------------------------------------------------------------------------
// Kernel 0: zero per-replay column accumulators
// ---------------------------------------------------------------------------
__global__ void zero_stats_kernel() {
    int t = threadIdx.x;
    if (t < C_DIM) { g_colsum[t] = 0.f; g_colsum2[t] = 0.f; }
}

// ---------------------------------------------------------------------------
// Kernel 2: warp-per-row LayerNorm + phi -> (cos,sin), fused column stats.
// No block barriers in the row loop; shuffle-only reductions.
// ---------------------------------------------------------------------------
__global__ void ln_phi_kernel(const float* __restrict__ lng, const float* __restrict__ lnb)
{
    __shared__ float sg[C_DIM], sb[C_DIM];
    const int tid  = threadIdx.x;
    const int lane = tid & 31;
    const int warp = tid >> 5;
    for (int i = tid; i < C_DIM; i += 256) { sg[i] = lng[i]; sb[i] = lnb[i]; }
    __syncthreads();

    float cs[32], cs2[32];
#pragma unroll
    for (int j = 0; j < 32; j++) { cs[j] = 0.f; cs2[j] = 0.f; }

    const int gw = blockIdx.x * 8 + warp;
    const int nw = gridDim.x * 8;

    for (long row = gw; row < N_ROWS; row += nw) {
        const float4* zr = (const float4*)(g_z + row * C_DIM);
        float4 v[8];
        float s = 0.f, s2 = 0.f;
#pragma unroll
        for (int j = 0; j < 8; j++) {
            v[j] = zr[lane + j * 32];
            s  += v[j].x + v[j].y + v[j].z + v[j].w;
            s2 += v[j].x*v[j].x + v[j].y*v[j].y + v[j].z*v[j].z + v[j].w*v[j].w;
        }
#pragma unroll
        for (int off = 16; off; off >>= 1) {
            s  += __shfl_xor_sync(0xffffffffu, s,  off);
            s2 += __shfl_xor_sync(0xffffffffu, s2, off);
        }
        const float mu   = s * (1.f / C_DIM);
        const float rstd = rsqrtf(s2 * (1.f / C_DIM) - mu * mu + LN_EPS);

        float4* qcr = (float4*)(g_qc + row * C_DIM);
        float4* qsr = (float4*)(g_qs + row * C_DIM);
#pragma unroll
        for (int j = 0; j < 8; j++) {
            const int cb = (lane + j * 32) * 4;
            float4 c4, s4;
            float zl, phi, sn, cn;

            zl = (v[j].x - mu) * rstd * sg[cb+0] + sb[cb+0];
            cs[j*4+0] += zl; cs2[j*4+0] += zl*zl;
            phi = 3.14159265358979323846f * tanhf(zl);
            sincosf(phi, &sn, &cn); c4.x = cn; s4.x = sn;

            zl = (v[j].y - mu) * rstd * sg[cb+1] + sb[cb+1];
            cs[j*4+1] += zl; cs2[j*4+1] += zl*zl;
            phi = 3.14159265358979323846f * tanhf(zl);
            sincosf(phi, &sn, &cn); c4.y = cn; s4.y = sn;

            zl = (v[j].z - mu) * rstd * sg[cb+2] + sb[cb+2];
            cs[j*4+2] += zl; cs2[j*4+2] += zl*zl;
            phi = 3.14159265358979323846f * tanhf(zl);
            sincosf(phi, &sn, &cn); c4.z = cn; s4.z = sn;

            zl = (v[j].w - mu) * rstd * sg[cb+3] + sb[cb+3];
            cs[j*4+3] += zl; cs2[j*4+3] += zl*zl;
            phi = 3.14159265358979323846f * tanhf(zl);
            sincosf(phi, &sn, &cn); c4.w = cn; s4.w = sn;

            qcr[lane + j * 32] = c4;
            qsr[lane + j * 32] = s4;
        }
    }
#pragma unroll
    for (int j = 0; j < 8; j++)
#pragma unroll
        for (int k = 0; k < 4; k++) {
            int col = (lane + j * 32) * 4 + k;
            atomicAdd(&g_colsum [col], cs[j*4+k]);
            atomicAdd(&g_colsum2[col], cs2[j*4+k]);
        }
}

// ---------------------------------------------------------------------------
// Kernel 3: column variance (ddof=1) + top-8
// ---------------------------------------------------------------------------
__global__ void topk_kernel()
{
    __shared__ float svar[C_DIM];
    const int tid = threadIdx.x;
    for (int c = tid; c < C_DIM; c += 256) {
        float s = g_colsum[c], s2 = g_colsum2[c];
        float mean = s * (1.f / N_ROWS);
        svar[c] = (s2 - s * mean) * (1.f / (N_ROWS - 1));
    }
    __syncthreads();
    if (tid < 32) {
        for (int p = 0; p < TOPK_K; p++) {
            float bvv = -3.0e38f; int bii = C_DIM;
            for (int c = tid; c < C_DIM; c += 32) {
                float vv = svar[c];
                if (vv > bvv || (vv == bvv && c < bii)) { bvv = vv; bii = c; }
            }
#pragma unroll
            for (int off = 16; off; off >>= 1) {
                float ov = __shfl_xor_sync(0xffffffffu, bvv, off);
                int   oi = __shfl_xor_sync(0xffffffffu, bii, off);
                if (ov > bvv || (ov == bvv && oi < bii)) { bvv = ov; bii = oi; }
            }
            if (tid == 0) { g_idx[p] = bii; svar[bii] = -3.0e38f; }
            __syncwarp();
        }
    }
}

// ---------------------------------------------------------------------------
// Kernel 5: interactions + alpha + bias + fused output LN
// out = LN( alpha*(g_q + qint @ Wi^T) + b_out )
// ---------------------------------------------------------------------------
__global__ __launch_bounds__(256)
void interact_ln_kernel(const float* __restrict__ Wout,
                        const float* __restrict__ bout,
                        const float* __restrict__ alphap,
                        const float* __restrict__ og,
                        const float* __restrict__ ob,
                        float* __restrict__ Out)
{
    __shared__ float sW[NPAIR * 256];   // [p][n]
    __shared__ float sb_[256], sg_[256], sob_[256];
    const int tid  = threadIdx.x;
    const int lane = tid & 31;
    const int warp = tid >> 5;

    for (int e = tid; e < NPAIR * 256; e += 256) {
        int p = e >> 8, n = e & 255;
        sW[p * 256 + n] = __ldg(&Wout[(long)n * QDIM_V + 2048 + p]);
    }
    sb_[tid] = bout[tid]; sg_[tid] = og[tid]; sob_[tid] = ob[tid];
    __syncthreads();

    const float alpha = __ldg(alphap);
    int idx8[8];
#pragma unroll
    for (int j = 0; j < 8; j++) idx8[j] = g_idx[j];

    const long rowBase = (long)blockIdx.x * 128 + warp * 16;
    for (int i = 0; i < 16; i++) {
        long row = rowBase + i;
        if (row >= N_ROWS) break;

        float qc8[8], qs8[8];
#pragma unroll
        for (int j = 0; j < 8; j++) {
            qc8[j] = __ldg(&g_qc[row * C_DIM + idx8[j]]);
            qs8[j] = __ldg(&g_qs[row * C_DIM + idx8[j]]);
        }
        float qint[NPAIR];
#pragma unroll
        for (int p = 0; p < NPAIR; p++)
            qint[p] = qc8[c_iu[p]] * qc8[c_ju[p]] + qs8[c_iu[p]] * qs8[c_ju[p]];

        const float* gq = g_q + row * OUT_DIM + lane * 8;
        float4 v0 = ((const float4*)gq)[0];
        float4 v1 = ((const float4*)gq)[1];
        float v[8] = {v0.x, v0.y, v0.z, v0.w, v1.x, v1.y, v1.z, v1.w};
#pragma unroll
        for (int p = 0; p < NPAIR; p++) {
            float q = qint[p];
            const float4* wp = (const float4*)(sW + p * 256 + lane * 8);
            float4 w0 = wp[0], w1 = wp[1];
            v[0] = fmaf(q, w0.x, v[0]); v[1] = fmaf(q, w0.y, v[1]);
            v[2] = fmaf(q, w0.z, v[2]); v[3] = fmaf(q, w0.w, v[3]);
            v[4] = fmaf(q, w1.x, v[4]); v[5] = fmaf(q, w1.y, v[5]);
            v[6] = fmaf(q, w1.z, v[6]); v[7] = fmaf(q, w1.w, v[7]);
        }
        float s = 0.f, s2 = 0.f;
#pragma unroll
        for (int j = 0; j < 8; j++) {
            float val = fmaf(alpha, v[j], sb_[lane * 8 + j]);
            v[j] = val; s += val; s2 += val * val;
        }
#pragma unroll
        for (int off = 16; off; off >>= 1) {
            s  += __shfl_xor_sync(0xffffffffu, s,  off);
            s2 += __shfl_xor_sync(0xffffffffu, s2, off);
        }
        float mu   = s * (1.f / OUT_DIM);
        float rstd = rsqrtf(s2 * (1.f / OUT_DIM) - mu * mu + LN_EPS);
        float o[8];
#pragma unroll
        for (int j = 0; j < 8; j++)
            o[j] = (v[j] - mu) * rstd * sg_[lane * 8 + j] + sob_[lane * 8 + j];
        float4* op = (float4*)(Out + row * OUT_DIM + lane * 8);
        op[0] = make_float4(o[0], o[1], o[2], o[3]);
        op[1] = make_float4(o[4], o[5], o[6], o[7]);
    }
}

// ---------------------------------------------------------------------------
// Launch sequence
// ---------------------------------------------------------------------------
extern "C" void kernel_launch(void* const* d_in, const int* in_sizes, int n_in,
                              void* d_out, int out_size) {
    const float* x     = (const float*)d_in[0];
    const float* Wproj = (const float*)d_in[1];
    const float* bproj = (const float*)d_in[2];
    const float* lng   = (const float*)d_in[3];
    const float* lnb   = (const float*)d_in[4];
    const float* alpha = (const float*)d_in[5];
    const float* Wout  = (const float*)d_in[6];
    const float* bout  = (const float*)d_in[7];
    const float* olng  = (const float*)d_in[8];
    const float* olnb  = (const float*)d_in[9];
    float* out = (float*)d_out;

    (void)in_sizes; (void)n_in; (void)out_size;

    const int SMEM_GEMM = 65536;
    cudaFuncSetAttribute((const void*)gemm_mma<16, false>,
                         cudaFuncAttributeMaxDynamicSharedMemorySize, SMEM_GEMM);
    cudaFuncSetAttribute((const void*)gemm_mma<32, true>,
                         cudaFuncAttributeMaxDynamicSharedMemorySize, SMEM_GEMM);

    const int MTILES = (N_ROWS + 127) / 128;   // 782

    zero_stats_kernel<<<1, 1024>>>();

    // GEMM1: g_z = x @ Wproj^T + bproj
    gemm_mma<16, false><<<dim3(8, MTILES), 512, SMEM_GEMM>>>(x, Wproj, bproj);

    // warp-per-row LN + phi (persistent-ish grid)
    ln_phi_kernel<<<296, 256>>>(lng, lnb);

    topk_kernel<<<1, 256>>>();

    // GEMM2: g_q = [Qc|Qs] @ Wout[:, 0:2048]^T
    gemm_mma<32, true><<<dim3(2, MTILES), 512, SMEM_GEMM>>>(nullptr, Wout, nullptr);

    // out = LN(alpha*(g_q + qint@Wi^T) + bout)
    interact_ln_kernel<<<MTILES, 256>>>(Wout, bout, alpha, olng, olnb, out);
}

// round 10
// speedup vs baseline: 1.1018x; 1.1018x over previous
#include <cuda_runtime.h>
#include <cuda_bf16.h>
#include <cstdint>

#define N_ROWS  100000
#define C_DIM   1024
#define OUT_DIM 256
#define TOPK_K  8
#define NPAIR   28
#define QDIM_V  2076
#define LN_EPS  1e-5f

// ---------------------------------------------------------------------------
// Device-global scratch (no cudaMalloc allowed)
// ---------------------------------------------------------------------------
__device__ float g_z [(size_t)N_ROWS * C_DIM];    // GEMM1 output (pre-LN)
__device__ float g_qc[(size_t)N_ROWS * C_DIM];    // cos(pi*tanh(z_ln))
__device__ float g_qs[(size_t)N_ROWS * C_DIM];    // sin(pi*tanh(z_ln))
__device__ float g_q [(size_t)N_ROWS * OUT_DIM];  // GEMM2 raw sums
__device__ float g_colsum [C_DIM];
__device__ float g_colsum2[C_DIM];
__device__ int   g_idx[TOPK_K];

// np.triu_indices(8, 1)
__constant__ int c_iu[NPAIR] = {0,0,0,0,0,0,0, 1,1,1,1,1,1, 2,2,2,2,2, 3,3,3,3, 4,4,4, 5,5, 6};
__constant__ int c_ju[NPAIR] = {1,2,3,4,5,6,7, 2,3,4,5,6,7, 3,4,5,6,7, 4,5,6,7, 5,6,7, 6,7, 7};

// ---------------------------------------------------------------------------
// Helpers
// ---------------------------------------------------------------------------
__device__ __forceinline__ uint32_t smem_u32(const void* p) {
    uint32_t a;
    asm("{ .reg .u64 t; cvta.to.shared.u64 t, %1; cvt.u32.u64 %0, t; }" : "=r"(a) : "l"(p));
    return a;
}
#define SWZ(o) ((o) ^ (((o) >> 3) & 0x70))

__device__ __forceinline__ void mma16816(float* d, const uint32_t* a, const uint32_t* b) {
    asm volatile("mma.sync.aligned.m16n8k16.row.col.f32.bf16.bf16.f32 "
        "{%0,%1,%2,%3}, {%4,%5,%6,%7}, {%8,%9}, {%0,%1,%2,%3};"
        : "+f"(d[0]), "+f"(d[1]), "+f"(d[2]), "+f"(d[3])
        : "r"(a[0]), "r"(a[1]), "r"(a[2]), "r"(a[3]), "r"(b[0]), "r"(b[1]));
}
__device__ __forceinline__ void ldsm_x4(uint32_t* r, uint32_t addr) {
    asm volatile("ldmatrix.sync.aligned.m8n8.x4.shared.b16 {%0,%1,%2,%3}, [%4];"
        : "=r"(r[0]), "=r"(r[1]), "=r"(r[2]), "=r"(r[3]) : "r"(addr));
}

// split fp32 x4 into bf16 hi/lo x4 (packed, memory order)
__device__ __forceinline__ void split4(float4 v, uint2& hi, uint2& lo) {
    __nv_bfloat16 h0 = __float2bfloat16_rn(v.x);
    __nv_bfloat16 h1 = __float2bfloat16_rn(v.y);
    __nv_bfloat16 h2 = __float2bfloat16_rn(v.z);
    __nv_bfloat16 h3 = __float2bfloat16_rn(v.w);
    __nv_bfloat16 l0 = __float2bfloat16_rn(v.x - __bfloat162float(h0));
    __nv_bfloat16 l1 = __float2bfloat16_rn(v.y - __bfloat162float(h1));
    __nv_bfloat16 l2 = __float2bfloat16_rn(v.z - __bfloat162float(h2));
    __nv_bfloat16 l3 = __float2bfloat16_rn(v.w - __bfloat162float(h3));
    hi.x = (uint32_t)__bfloat16_as_ushort(h0) | ((uint32_t)__bfloat16_as_ushort(h1) << 16);
    hi.y = (uint32_t)__bfloat16_as_ushort(h2) | ((uint32_t)__bfloat16_as_ushort(h3) << 16);
    lo.x = (uint32_t)__bfloat16_as_ushort(l0) | ((uint32_t)__bfloat16_as_ushort(l1) << 16);
    lo.y = (uint32_t)__bfloat16_as_ushort(l2) | ((uint32_t)__bfloat16_as_ushort(l3) << 16);
}

// ---------------------------------------------------------------------------
// Split-bf16 mma.sync GEMM, A-only register prefetch (16 regs held across
// compute; B is L2-resident weights, loaded at loop top).
// Block 128x128, 512 threads, warp tile 32x32 (4x4 warp grid).
// A*B ~= Ah*Bh + Ah*Bl + Al*Bh  (fp32 accumulators)
// smem stage (64KB): Ah@0 | Al@16K | Bh@32K | Bl@48K, SW128 swizzle, K-chunk 64.
// G2=false: g_z = x @ Wproj^T + bias.  G2=true: g_q = [Qc|Qs] @ Wout[:, :2048]^T
// ---------------------------------------------------------------------------
template<int KT, bool G2>
__global__ void __launch_bounds__(512, 1)
gemm_mma(const float* __restrict__ A0, const float* __restrict__ B0,
         const float* __restrict__ bias)
{
    extern __shared__ char smem[];
    const uint32_t sbase = smem_u32(smem);
    const int tid  = threadIdx.x;
    const int lane = tid & 31;
    const int warp = tid >> 5;
    const int wm   = warp >> 2;            // 0..3
    const int wn   = warp & 3;             // 0..3
    const int n0   = blockIdx.x * 128;
    const long m0  = (long)blockIdx.y * 128;
    const long sA  = C_DIM;
    const long sB  = G2 ? QDIM_V : C_DIM;

    float acc[2][4][4];
#pragma unroll
    for (int mt = 0; mt < 2; mt++)
#pragma unroll
        for (int nt = 0; nt < 4; nt++)
#pragma unroll
            for (int j = 0; j < 4; j++) acc[mt][nt][j] = 0.f;

    // per-thread fill coordinates (4 iterations x (A,B))
    const int f_r = tid >> 4;              // 0..31 (+32*i)
    const int f_c = tid & 15;              // 0..15

    auto load_A = [&](int kt, float4* va) {
        const float* Ap; long acol;
        if (G2) {
            if (kt < KT / 2) { Ap = (const float*)g_qc; acol = (long)kt * 64; }
            else             { Ap = (const float*)g_qs; acol = (long)(kt - KT / 2) * 64; }
        } else { Ap = A0; acol = (long)kt * 64; }
#pragma unroll
        for (int i = 0; i < 4; i++) {
            long arow = m0 + f_r + i * 32;
            va[i] = (arow < N_ROWS)
                ? __ldg((const float4*)(Ap + arow * sA + acol + f_c * 4))
                : make_float4(0.f, 0.f, 0.f, 0.f);
        }
    };
    auto load_B = [&](int kt, float4* vb) {
        const long bcol = (long)kt * 64;
#pragma unroll
        for (int i = 0; i < 4; i++)
            vb[i] = __ldg((const float4*)(B0 + (long)(n0 + f_r + i * 32) * sB + bcol + f_c * 4));
    };

    // ldmatrix per-lane address precompute (swizzle XOR depends only on row)
    const int a_r  = lane & 15;
    const int a_kb = (lane >> 4) << 4;
    const int b_r  = (lane & 7) | ((lane >> 4) << 3);
    const int b_kb = ((lane >> 3) & 1) << 4;
    uint32_t aoff[2], axr[2], boff[2], bxr[2];
#pragma unroll
    for (int mt = 0; mt < 2; mt++) {
        uint32_t o = (uint32_t)((wm * 32 + mt * 16 + a_r) * 128 + a_kb);
        axr[mt] = (o >> 3) & 0x70; aoff[mt] = o;
    }
#pragma unroll
    for (int bt = 0; bt < 2; bt++) {
        uint32_t o = (uint32_t)((wn * 32 + bt * 16 + b_r) * 128 + b_kb);
        bxr[bt] = (o >> 3) & 0x70; boff[bt] = o;
    }

    float4 va[4];
    load_A(0, va);

    for (int kt = 0; kt < KT; kt++) {
        // ---- B loads for this chunk (L2-resident weights, short latency) ----
        float4 vb[4];
        load_B(kt, vb);

        // ---- store tiles -> bf16 hi/lo swizzled smem ----
#pragma unroll
        for (int i = 0; i < 4; i++) {
            int r = f_r + i * 32;
            uint32_t off = SWZ((uint32_t)(r * 128 + f_c * 8));
            uint2 hi, lo;
            split4(va[i], hi, lo);
            *(uint2*)(smem + off)         = hi;
            *(uint2*)(smem + 16384 + off) = lo;
            split4(vb[i], hi, lo);
            *(uint2*)(smem + 32768 + off) = hi;
            *(uint2*)(smem + 49152 + off) = lo;
        }
        __syncthreads();

        // ---- prefetch next A chunk (DRAM latency hides under compute) ----
        float4 na[4];
        if (kt + 1 < KT) load_A(kt + 1, na);

        // ---- compute: 4 k16 steps x 3 split terms ----
#pragma unroll
        for (int ks = 0; ks < 4; ks++) {
            uint32_t ah[2][4], al[2][4], bh[4][2], bl[4][2];
#pragma unroll
            for (int mt = 0; mt < 2; mt++) {
                uint32_t ad = sbase + ((aoff[mt] + ks * 32) ^ axr[mt]);
                ldsm_x4(ah[mt], ad);
                ldsm_x4(al[mt], ad + 16384);
            }
#pragma unroll
            for (int bt = 0; bt < 2; bt++) {
                uint32_t bd = sbase + 32768 + ((boff[bt] + ks * 32) ^ bxr[bt]);
                uint32_t q[4];
                ldsm_x4(q, bd);
                bh[2*bt][0] = q[0]; bh[2*bt][1] = q[1];
                bh[2*bt+1][0] = q[2]; bh[2*bt+1][1] = q[3];
                ldsm_x4(q, bd + 16384);
                bl[2*bt][0] = q[0]; bl[2*bt][1] = q[1];
                bl[2*bt+1][0] = q[2]; bl[2*bt+1][1] = q[3];
            }
#pragma unroll
            for (int mt = 0; mt < 2; mt++)
#pragma unroll
                for (int nt = 0; nt < 4; nt++) {
                    mma16816(acc[mt][nt], ah[mt], bh[nt]);
                    mma16816(acc[mt][nt], ah[mt], bl[nt]);
                    mma16816(acc[mt][nt], al[mt], bh[nt]);
                }
        }

        if (kt + 1 < KT) {
#pragma unroll
            for (int i = 0; i < 4; i++) va[i] = na[i];
        }
        __syncthreads();
    }

    // ---- epilogue: write fp32 (optionally + bias) ----
    float* Outp = G2 ? (float*)g_q : (float*)g_z;
    const long sOut = G2 ? OUT_DIM : C_DIM;
    const int qr = lane >> 2;
    const int qc = (lane & 3) * 2;
#pragma unroll
    for (int mt = 0; mt < 2; mt++)
#pragma unroll
        for (int nt = 0; nt < 4; nt++) {
            long m = m0 + wm * 32 + mt * 16 + qr;
            int  n = n0 + wn * 32 + nt * 8 + qc;
            float2 bv = make_float2(0.f, 0.f);
            if (!G2) bv = *(const float2*)(bias + n);
            if (m < N_ROWS) {
                float2 v = make_float2(acc[mt][nt][0] + bv.x, acc[mt][nt][1] + bv.y);
                *(float2*)(Outp + m * sOut + n) = v;
            }
            if (m + 8 < N_ROWS) {
                float2 v = make_float2(acc[mt][nt][2] + bv.x, acc[mt][nt][3] + bv.y);
                *(float2*)(Outp + (m + 8) * sOut + n) = v;
            }
        }
}

// ---------------------------------------------------------------------------
// Kernel 0: zero per-replay column accumulators
// ---------------------------------------------------------------------------
__global__ void zero_stats_kernel() {
    int t = threadIdx.x;
    if (t < C_DIM) { g_colsum[t] = 0.f; g_colsum2[t] = 0.f; }
}

// ---------------------------------------------------------------------------
// Kernel 2: warp-per-row LayerNorm + phi -> (cos,sin), fused column stats.
// No block barriers in the row loop; shuffle-only reductions.
// ---------------------------------------------------------------------------
__global__ void ln_phi_kernel(const float* __restrict__ lng, const float* __restrict__ lnb)
{
    __shared__ float sg[C_DIM], sb[C_DIM];
    const int tid  = threadIdx.x;
    const int lane = tid & 31;
    const int warp = tid >> 5;
    for (int i = tid; i < C_DIM; i += 256) { sg[i] = lng[i]; sb[i] = lnb[i]; }
    __syncthreads();

    float cs[32], cs2[32];
#pragma unroll
    for (int j = 0; j < 32; j++) { cs[j] = 0.f; cs2[j] = 0.f; }

    const int gw = blockIdx.x * 8 + warp;
    const int nw = gridDim.x * 8;

    for (long row = gw; row < N_ROWS; row += nw) {
        const float4* zr = (const float4*)(g_z + row * C_DIM);
        float4 v[8];
        float s = 0.f, s2 = 0.f;
#pragma unroll
        for (int j = 0; j < 8; j++) {
            v[j] = zr[lane + j * 32];
            s  += v[j].x + v[j].y + v[j].z + v[j].w;
            s2 += v[j].x*v[j].x + v[j].y*v[j].y + v[j].z*v[j].z + v[j].w*v[j].w;
        }
#pragma unroll
        for (int off = 16; off; off >>= 1) {
            s  += __shfl_xor_sync(0xffffffffu, s,  off);
            s2 += __shfl_xor_sync(0xffffffffu, s2, off);
        }
        const float mu   = s * (1.f / C_DIM);
        const float rstd = rsqrtf(s2 * (1.f / C_DIM) - mu * mu + LN_EPS);

        float4* qcr = (float4*)(g_qc + row * C_DIM);
        float4* qsr = (float4*)(g_qs + row * C_DIM);
#pragma unroll
        for (int j = 0; j < 8; j++) {
            const int cb = (lane + j * 32) * 4;
            float4 c4, s4;
            float zl, phi, sn, cn;

            zl = (v[j].x - mu) * rstd * sg[cb+0] + sb[cb+0];
            cs[j*4+0] += zl; cs2[j*4+0] += zl*zl;
            phi = 3.14159265358979323846f * tanhf(zl);
            sincosf(phi, &sn, &cn); c4.x = cn; s4.x = sn;

            zl = (v[j].y - mu) * rstd * sg[cb+1] + sb[cb+1];
            cs[j*4+1] += zl; cs2[j*4+1] += zl*zl;
            phi = 3.14159265358979323846f * tanhf(zl);
            sincosf(phi, &sn, &cn); c4.y = cn; s4.y = sn;

            zl = (v[j].z - mu) * rstd * sg[cb+2] + sb[cb+2];
            cs[j*4+2] += zl; cs2[j*4+2] += zl*zl;
            phi = 3.14159265358979323846f * tanhf(zl);
            sincosf(phi, &sn, &cn); c4.z = cn; s4.z = sn;

            zl = (v[j].w - mu) * rstd * sg[cb+3] + sb[cb+3];
            cs[j*4+3] += zl; cs2[j*4+3] += zl*zl;
            phi = 3.14159265358979323846f * tanhf(zl);
            sincosf(phi, &sn, &cn); c4.w = cn; s4.w = sn;

            qcr[lane + j * 32] = c4;
            qsr[lane + j * 32] = s4;
        }
    }
#pragma unroll
    for (int j = 0; j < 8; j++)
#pragma unroll
        for (int k = 0; k < 4; k++) {
            int col = (lane + j * 32) * 4 + k;
            atomicAdd(&g_colsum [col], cs[j*4+k]);
            atomicAdd(&g_colsum2[col], cs2[j*4+k]);
        }
}

// ---------------------------------------------------------------------------
// Kernel 3: column variance (ddof=1) + top-8
// ---------------------------------------------------------------------------
__global__ void topk_kernel()
{
    __shared__ float svar[C_DIM];
    const int tid = threadIdx.x;
    for (int c = tid; c < C_DIM; c += 256) {
        float s = g_colsum[c], s2 = g_colsum2[c];
        float mean = s * (1.f / N_ROWS);
        svar[c] = (s2 - s * mean) * (1.f / (N_ROWS - 1));
    }
    __syncthreads();
    if (tid < 32) {
        for (int p = 0; p < TOPK_K; p++) {
            float bvv = -3.0e38f; int bii = C_DIM;
            for (int c = tid; c < C_DIM; c += 32) {
                float vv = svar[c];
                if (vv > bvv || (vv == bvv && c < bii)) { bvv = vv; bii = c; }
            }
#pragma unroll
            for (int off = 16; off; off >>= 1) {
                float ov = __shfl_xor_sync(0xffffffffu, bvv, off);
                int   oi = __shfl_xor_sync(0xffffffffu, bii, off);
                if (ov > bvv || (ov == bvv && oi < bii)) { bvv = ov; bii = oi; }
            }
            if (tid == 0) { g_idx[p] = bii; svar[bii] = -3.0e38f; }
            __syncwarp();
        }
    }
}

// ---------------------------------------------------------------------------
// Kernel 5: interactions + alpha + bias + fused output LN
// out = LN( alpha*(g_q + qint @ Wi^T) + b_out )
// ---------------------------------------------------------------------------
__global__ __launch_bounds__(256)
void interact_ln_kernel(const float* __restrict__ Wout,
                        const float* __restrict__ bout,
                        const float* __restrict__ alphap,
                        const float* __restrict__ og,
                        const float* __restrict__ ob,
                        float* __restrict__ Out)
{
    __shared__ float sW[NPAIR * 256];   // [p][n]
    __shared__ float sb_[256], sg_[256], sob_[256];
    const int tid  = threadIdx.x;
    const int lane = tid & 31;
    const int warp = tid >> 5;

    for (int e = tid; e < NPAIR * 256; e += 256) {
        int p = e >> 8, n = e & 255;
        sW[p * 256 + n] = __ldg(&Wout[(long)n * QDIM_V + 2048 + p]);
    }
    sb_[tid] = bout[tid]; sg_[tid] = og[tid]; sob_[tid] = ob[tid];
    __syncthreads();

    const float alpha = __ldg(alphap);
    int idx8[8];
#pragma unroll
    for (int j = 0; j < 8; j++) idx8[j] = g_idx[j];

    const long rowBase = (long)blockIdx.x * 128 + warp * 16;
    for (int i = 0; i < 16; i++) {
        long row = rowBase + i;
        if (row >= N_ROWS) break;

        float qc8[8], qs8[8];
#pragma unroll
        for (int j = 0; j < 8; j++) {
            qc8[j] = __ldg(&g_qc[row * C_DIM + idx8[j]]);
            qs8[j] = __ldg(&g_qs[row * C_DIM + idx8[j]]);
        }
        float qint[NPAIR];
#pragma unroll
        for (int p = 0; p < NPAIR; p++)
            qint[p] = qc8[c_iu[p]] * qc8[c_ju[p]] + qs8[c_iu[p]] * qs8[c_ju[p]];

        const float* gq = g_q + row * OUT_DIM + lane * 8;
        float4 v0 = ((const float4*)gq)[0];
        float4 v1 = ((const float4*)gq)[1];
        float v[8] = {v0.x, v0.y, v0.z, v0.w, v1.x, v1.y, v1.z, v1.w};
#pragma unroll
        for (int p = 0; p < NPAIR; p++) {
            float q = qint[p];
            const float4* wp = (const float4*)(sW + p * 256 + lane * 8);
            float4 w0 = wp[0], w1 = wp[1];
            v[0] = fmaf(q, w0.x, v[0]); v[1] = fmaf(q, w0.y, v[1]);
            v[2] = fmaf(q, w0.z, v[2]); v[3] = fmaf(q, w0.w, v[3]);
            v[4] = fmaf(q, w1.x, v[4]); v[5] = fmaf(q, w1.y, v[5]);
            v[6] = fmaf(q, w1.z, v[6]); v[7] = fmaf(q, w1.w, v[7]);
        }
        float s = 0.f, s2 = 0.f;
#pragma unroll
        for (int j = 0; j < 8; j++) {
            float val = fmaf(alpha, v[j], sb_[lane * 8 + j]);
            v[j] = val; s += val; s2 += val * val;
        }
#pragma unroll
        for (int off = 16; off; off >>= 1) {
            s  += __shfl_xor_sync(0xffffffffu, s,  off);
            s2 += __shfl_xor_sync(0xffffffffu, s2, off);
        }
        float mu   = s * (1.f / OUT_DIM);
        float rstd = rsqrtf(s2 * (1.f / OUT_DIM) - mu * mu + LN_EPS);
        float o[8];
#pragma unroll
        for (int j = 0; j < 8; j++)
            o[j] = (v[j] - mu) * rstd * sg_[lane * 8 + j] + sob_[lane * 8 + j];
        float4* op = (float4*)(Out + row * OUT_DIM + lane * 8);
        op[0] = make_float4(o[0], o[1], o[2], o[3]);
        op[1] = make_float4(o[4], o[5], o[6], o[7]);
    }
}

// ---------------------------------------------------------------------------
// Launch sequence
// ---------------------------------------------------------------------------
extern "C" void kernel_launch(void* const* d_in, const int* in_sizes, int n_in,
                              void* d_out, int out_size) {
    const float* x     = (const float*)d_in[0];
    const float* Wproj = (const float*)d_in[1];
    const float* bproj = (const float*)d_in[2];
    const float* lng   = (const float*)d_in[3];
    const float* lnb   = (const float*)d_in[4];
    const float* alpha = (const float*)d_in[5];
    const float* Wout  = (const float*)d_in[6];
    const float* bout  = (const float*)d_in[7];
    const float* olng  = (const float*)d_in[8];
    const float* olnb  = (const float*)d_in[9];
    float* out = (float*)d_out;

    (void)in_sizes; (void)n_in; (void)out_size;

    const int SMEM_GEMM = 65536;
    cudaFuncSetAttribute((const void*)gemm_mma<16, false>,
                         cudaFuncAttributeMaxDynamicSharedMemorySize, SMEM_GEMM);
    cudaFuncSetAttribute((const void*)gemm_mma<32, true>,
                         cudaFuncAttributeMaxDynamicSharedMemorySize, SMEM_GEMM);

    const int MTILES = (N_ROWS + 127) / 128;   // 782

    zero_stats_kernel<<<1, 1024>>>();

    // GEMM1: g_z = x @ Wproj^T + bproj
    gemm_mma<16, false><<<dim3(8, MTILES), 512, SMEM_GEMM>>>(x, Wproj, bproj);

    // warp-per-row LN + phi
    ln_phi_kernel<<<296, 256>>>(lng, lnb);

    topk_kernel<<<1, 256>>>();

    // GEMM2: g_q = [Qc|Qs] @ Wout[:, 0:2048]^T
    gemm_mma<32, true><<<dim3(2, MTILES), 512, SMEM_GEMM>>>(nullptr, Wout, nullptr);

    // out = LN(alpha*(g_q + qint@Wi^T) + bout)
    interact_ln_kernel<<<MTILES, 256>>>(Wout, bout, alpha, olng, olnb, out);
}